// round 14
// baseline (speedup 1.0000x reference)
#include <cuda_runtime.h>
#include <cuda_fp16.h>
#include <cstdint>
#include <math.h>

#define SS  2048
#define BB  16
#define DD  1024
#define HH  8
#define DHH 128
#define MM  (SS*BB)        // 32768 token rows
#define BDD (BB*DD)        // 16384 (s-stride for DD-stride matrices)
#define NQKV 3072
#define SSTR (BB*NQKV)     // 49152 (s-stride inside qkv)

// ---------------- scratch (device globals; allocation-free) ----------------
__device__ __half g_h   [(size_t)MM*DD];
__device__ __half g_qkv [(size_t)MM*NQKV];  // [m][ q(1024) | k(1024) | v(1024) ]
__device__ __half g_att [(size_t)MM*DD];
__device__ __half g_w   [4][(size_t)DD*DD]; // wq|wk|wv|wo contiguous
__device__ float  g_bqkv[NQKV];
__device__ __half g_pe  [(size_t)SS*DD];    // positional encoding table
__device__ __half g_kvT [BB*HH*DHH*DHH];    // kv^T: [pair][e][d] fp16
__device__ float  g_z   [BB*HH*DHH];

// ---------------- helpers ----------------
__device__ __forceinline__ uint32_t smem_u32(const void* p) {
    uint32_t a;
    asm("{ .reg .u64 t; cvta.to.shared.u64 t, %1; cvt.u32.u64 %0, t; }" : "=r"(a) : "l"(p));
    return a;
}
__device__ __forceinline__ void ldsm4(uint32_t* r, uint32_t a) {
    asm volatile("ldmatrix.sync.aligned.m8n8.x4.shared.b16 {%0,%1,%2,%3}, [%4];"
        : "=r"(r[0]), "=r"(r[1]), "=r"(r[2]), "=r"(r[3]) : "r"(a));
}
__device__ __forceinline__ void ldsm2(uint32_t* r, uint32_t a) {
    asm volatile("ldmatrix.sync.aligned.m8n8.x2.shared.b16 {%0,%1}, [%2];"
        : "=r"(r[0]), "=r"(r[1]) : "r"(a));
}
__device__ __forceinline__ void mma16816h(float* c, const uint32_t* a, const uint32_t* b) {
    asm volatile("mma.sync.aligned.m16n8k16.row.col.f32.f16.f16.f32 "
        "{%0,%1,%2,%3}, {%4,%5,%6,%7}, {%8,%9}, {%0,%1,%2,%3};"
        : "+f"(c[0]), "+f"(c[1]), "+f"(c[2]), "+f"(c[3])
        : "r"(a[0]), "r"(a[1]), "r"(a[2]), "r"(a[3]), "r"(b[0]), "r"(b[1]));
}
#define CPA_CA(dst, src) asm volatile("cp.async.ca.shared.global [%0], [%1], 16;" :: "r"(dst), "l"(src) : "memory")
#define CPC()  asm volatile("cp.async.commit_group;" ::: "memory")
#define CPW0() asm volatile("cp.async.wait_group 0;" ::: "memory")
#define CPW1() asm volatile("cp.async.wait_group 1;" ::: "memory")

// ---------------------------------------------------------------------------
// PE table: pe[s][d], b-independent (16x fewer sin/cos than fused version)
// ---------------------------------------------------------------------------
__global__ void pe_table(__half* __restrict__ pe) {
    size_t i4 = (size_t)blockIdx.x * blockDim.x + threadIdx.x;   // SS*DD/4 total
    size_t e  = i4 * 4;
    int d = (int)(e % DD);
    int s = (int)(e / DD);
    const float cc = -9.210340371976184f / (float)DD;
    float a0 = (float)s * expf((float)d * cc);
    float a1 = (float)s * expf((float)(d + 2) * cc);
    __half2* pp = reinterpret_cast<__half2*>(pe) + i4*2;
    pp[0] = __floats2half2_rn(sinf(a0), cosf(a0));
    pp[1] = __floats2half2_rn(sinf(a1), cosf(a1));
}

// h = x + pe[s]  (pure streaming; pe row L1/L2-resident across b)
__global__ void pe_add_t(const float* __restrict__ x, const __half* __restrict__ pe,
                         __half* __restrict__ h) {
    size_t i4 = (size_t)blockIdx.x * blockDim.x + threadIdx.x;   // MM*DD/4 total
    size_t e  = i4 * 4;
    int d = (int)(e % DD);
    int m = (int)(e / DD);
    int s = m / BB;
    float4 xv = reinterpret_cast<const float4*>(x)[i4];
    uint2 pr = *reinterpret_cast<const uint2*>(pe + (size_t)s*DD + d);
    __half2 p0 = *reinterpret_cast<__half2*>(&pr.x);
    __half2 p1 = *reinterpret_cast<__half2*>(&pr.y);
    float2 pf0 = __half22float2(p0);
    float2 pf1 = __half22float2(p1);
    __half2* hp = reinterpret_cast<__half2*>(h) + i4*2;
    hp[0] = __floats2half2_rn(xv.x + pf0.x, xv.y + pf0.y);
    hp[1] = __floats2half2_rn(xv.z + pf1.x, xv.w + pf1.y);
}

// all 4 weight conversions + qkv bias concat in one launch
__global__ void conv_all(const float* __restrict__ w0, const float* __restrict__ w1,
                         const float* __restrict__ w2, const float* __restrict__ w3,
                         const float* __restrict__ bq, const float* __restrict__ bk,
                         const float* __restrict__ bv,
                         __half* __restrict__ dst, float* __restrict__ bqkv) {
    const size_t per = (size_t)DD*DD/4;
    size_t i4 = (size_t)blockIdx.x * blockDim.x + threadIdx.x;
    int wi = (int)(i4 / per);
    size_t off = i4 % per;
    const float* src = (wi == 0) ? w0 : (wi == 1) ? w1 : (wi == 2) ? w2 : w3;
    float4 v = reinterpret_cast<const float4*>(src)[off];
    __half2* dp = reinterpret_cast<__half2*>(dst + (size_t)wi*DD*DD) + off*2;
    dp[0] = __floats2half2_rn(v.x, v.y);
    dp[1] = __floats2half2_rn(v.z, v.w);
    if (i4 < NQKV) {
        int j = (int)i4;
        bqkv[j] = (j < DD) ? bq[j] : (j < 2*DD) ? bk[j - DD] : bv[j - 2*DD];
    }
}

// ---------------------------------------------------------------------------
// 3-stage cp.async.ca fp16 GEMM, single __syncthreads per chunk.
// CTA 128x128, 256 thr (2x4 warps, warp tile 64x32), KC=32.
// MODE 0: A=h; B=wqkv; C=qkv fp16 ldc=NQKV; elu+1 iff ncol<2048.
// MODE 1: A=att; B=wo; C=fp32 out ldc=DD.
// ---------------------------------------------------------------------------
#define KC2   32
#define NKC   (DD/KC2)        // 32
#define TPADB 80              // bytes per padded row (64B data + 16B pad)
#define TBYTES (128*TPADB)    // 10240
#define STG    (2*TBYTES)     // 20480 per stage (A+B)
#define GSMEM  (3*STG)        // 61440 -> 2 CTAs/SM (regs permitting)

template<int MODE>
__global__ void __launch_bounds__(256) gemm_cpa(
    const __half* __restrict__ Ag, const __half* __restrict__ Bg,
    const float* __restrict__ bias, void* __restrict__ Cv) {
    extern __shared__ char sm[];
    const int tid = threadIdx.x;
    const int l   = tid & 31;
    const int wid = tid >> 5;
    const int wm  = wid >> 2;       // 0..1
    const int wn  = wid & 3;        // 0..3
    const int m0  = blockIdx.y * 128;
    const int n0  = blockIdx.x * 128;

    const int lrow0 = tid >> 2;      // 0..63
    const int lcol  = tid & 3;       // 16B chunk
    const uint32_t sbase = smem_u32(sm);

    const __half* A1 = Ag + (size_t)(m0 + lrow0)      * DD + lcol*8;
    const __half* A2 = Ag + (size_t)(m0 + lrow0 + 64) * DD + lcol*8;
    const __half* B1 = Bg + (size_t)(n0 + lrow0)      * DD + lcol*8;
    const __half* B2 = Bg + (size_t)(n0 + lrow0 + 64) * DD + lcol*8;
    const uint32_t dA1 = (uint32_t)(lrow0*TPADB + lcol*16);
    const uint32_t dA2 = (uint32_t)((lrow0+64)*TPADB + lcol*16);
    const uint32_t dB1 = TBYTES + dA1;
    const uint32_t dB2 = TBYTES + dA2;

    // prologue: chunks 0,1 -> stages 0,1
#pragma unroll
    for (int s = 0; s < 2; s++) {
        const uint32_t sb = sbase + s*STG;
        const int ko = s*KC2;
        CPA_CA(sb + dA1, A1 + ko);  CPA_CA(sb + dA2, A2 + ko);
        CPA_CA(sb + dB1, B1 + ko);  CPA_CA(sb + dB2, B2 + ko);
        CPC();
    }

    float acc[4][4][4];
#pragma unroll
    for (int mt = 0; mt < 4; mt++)
#pragma unroll
        for (int nt = 0; nt < 4; nt++)
#pragma unroll
            for (int i = 0; i < 4; i++) acc[mt][nt][i] = 0.f;

    const uint32_t aoff0 = (uint32_t)((wm*64 + (l & 15)) * TPADB + ((l >> 4) << 4));
    // B ldsm4 over nt-pairs (R12-validated mapping)
    const uint32_t boff0 = (uint32_t)(TBYTES
        + (wn*32 + (l & 7) + ((l >> 4) & 1)*8) * TPADB
        + (((l >> 3) & 1) << 4));

    int stage = 0;
    for (int c = 0; c < NKC; c++) {
        if (c + 2 < NKC) CPW1(); else CPW0();   // chunk c landed
        __syncthreads();                        // all warps done reading stage (c+2)%3 (iter c-1 compute)
        if (c + 2 < NKC) {
            int ws = stage + 2; if (ws >= 3) ws -= 3;
            const uint32_t sb = sbase + ws*STG;
            const int ko = (c + 2)*KC2;
            CPA_CA(sb + dA1, A1 + ko);  CPA_CA(sb + dA2, A2 + ko);
            CPA_CA(sb + dB1, B1 + ko);  CPA_CA(sb + dB2, B2 + ko);
            CPC();
        }

        const uint32_t cb = sbase + stage*STG;
#pragma unroll
        for (int ks = 0; ks < 2; ks++) {
            uint32_t ah[4][4], bh[4][2];
#pragma unroll
            for (int mt = 0; mt < 4; mt++) ldsm4(ah[mt], cb + aoff0 + ks*32 + mt*16*TPADB);
#pragma unroll
            for (int np = 0; np < 2; np++) {
                uint32_t b4[4];
                ldsm4(b4, cb + boff0 + ks*32 + np*16*TPADB);
                bh[2*np][0]   = b4[0]; bh[2*np][1]   = b4[1];
                bh[2*np+1][0] = b4[2]; bh[2*np+1][1] = b4[3];
            }
#pragma unroll
            for (int mt = 0; mt < 4; mt++)
#pragma unroll
                for (int nt = 0; nt < 4; nt++)
                    mma16816h(acc[mt][nt], ah[mt], bh[nt]);
        }
        stage++; if (stage == 3) stage = 0;
    }

    // epilogue
    const int gi = l >> 2, ti = l & 3;
#pragma unroll
    for (int mt = 0; mt < 4; mt++) {
        const int ra = m0 + wm*64 + mt*16 + gi;
        const int rb = ra + 8;
#pragma unroll
        for (int nt = 0; nt < 4; nt++) {
            const int ncol = n0 + wn*32 + nt*8 + ti*2;
            const float b0 = bias[ncol], b1 = bias[ncol + 1];
            float u0 = acc[mt][nt][0] + b0;
            float u1 = acc[mt][nt][1] + b1;
            float u2 = acc[mt][nt][2] + b0;
            float u3 = acc[mt][nt][3] + b1;
            if (MODE == 0) {
                if (ncol < 2048) {   // q,k: elu+1
                    u0 = (u0 > 0.f) ? (u0 + 1.f) : expf(u0);
                    u1 = (u1 > 0.f) ? (u1 + 1.f) : expf(u1);
                    u2 = (u2 > 0.f) ? (u2 + 1.f) : expf(u2);
                    u3 = (u3 > 0.f) ? (u3 + 1.f) : expf(u3);
                }
                __half* C = (__half*)Cv;
                *reinterpret_cast<__half2*>(C + (size_t)ra*NQKV + ncol) = __floats2half2_rn(u0, u1);
                *reinterpret_cast<__half2*>(C + (size_t)rb*NQKV + ncol) = __floats2half2_rn(u2, u3);
            } else {
                float* C = (float*)Cv;
                float2 o01; o01.x = u0; o01.y = u1;
                float2 o23; o23.x = u2; o23.y = u3;
                *reinterpret_cast<float2*>(C + (size_t)ra*DD + ncol) = o01;
                *reinterpret_cast<float2*>(C + (size_t)rb*DD + ncol) = o23;
            }
        }
    }
}

// ---------------------------------------------------------------------------
// kvz via MMA: per pair, kvT[e][d] = sum_s v[s,e]*pk[s,d]; z[d] = sum_s pk[s,d]
// ---------------------------------------------------------------------------
#define KVSTG (2*TBYTES)
#define KVSMEM (2*KVSTG)   // 40960

__global__ void __launch_bounds__(256) kvz_mma(const __half* __restrict__ qkv,
                                               __half* __restrict__ kvT,
                                               float* __restrict__ z) {
    extern __shared__ char sm[];
    __shared__ float zsm[DHH];
    const int pair = blockIdx.x;
    const size_t base = (size_t)(pair / HH) * NQKV + (size_t)(pair % HH) * DHH;
    const __half* pk = qkv + DD   + base;
    const __half* vv = qkv + 2*DD + base;
    const int tid = threadIdx.x;
    const int l   = tid & 31;
    const int wid = tid >> 5;
    const int wm  = wid >> 2;
    const int wn  = wid & 3;

    if (tid < DHH) zsm[tid] = 0.f;

    const int s1 = tid >> 4,        d01 = (tid & 15) << 3;
    const int s2 = (tid + 256) >> 4;
    float zpart[8];
#pragma unroll
    for (int i = 0; i < 8; i++) zpart[i] = 0.f;

    {
        uint4 va1 = *reinterpret_cast<const uint4*>(vv + (size_t)s1*SSTR + d01);
        uint4 va2 = *reinterpret_cast<const uint4*>(vv + (size_t)s2*SSTR + d01);
        uint4 pa1 = *reinterpret_cast<const uint4*>(pk + (size_t)s1*SSTR + d01);
        uint4 pa2 = *reinterpret_cast<const uint4*>(pk + (size_t)s2*SSTR + d01);
        __half h8[8];
        *reinterpret_cast<uint4*>(h8) = va1;
#pragma unroll
        for (int j = 0; j < 8; j++) { int i = (j + l) & 7;
            *reinterpret_cast<__half*>(sm + (d01+i)*TPADB + s1*2) = h8[i]; }
        *reinterpret_cast<uint4*>(h8) = va2;
#pragma unroll
        for (int j = 0; j < 8; j++) { int i = (j + l) & 7;
            *reinterpret_cast<__half*>(sm + (d01+i)*TPADB + s2*2) = h8[i]; }
        *reinterpret_cast<uint4*>(h8) = pa1;
#pragma unroll
        for (int j = 0; j < 8; j++) { int i = (j + l) & 7;
            zpart[i] += __half2float(h8[i]);
            *reinterpret_cast<__half*>(sm + TBYTES + (d01+i)*TPADB + s1*2) = h8[i]; }
        *reinterpret_cast<uint4*>(h8) = pa2;
#pragma unroll
        for (int j = 0; j < 8; j++) { int i = (j + l) & 7;
            zpart[i] += __half2float(h8[i]);
            *reinterpret_cast<__half*>(sm + TBYTES + (d01+i)*TPADB + s2*2) = h8[i]; }
    }
    __syncthreads();

    float acc[4][4][4];
#pragma unroll
    for (int mt = 0; mt < 4; mt++)
#pragma unroll
        for (int nt = 0; nt < 4; nt++)
#pragma unroll
            for (int i = 0; i < 4; i++) acc[mt][nt][i] = 0.f;

    const uint32_t sbase = smem_u32(sm);
    const uint32_t aoff0 = (uint32_t)((wm*64 + (l & 15)) * TPADB + ((l >> 4) << 4));
    const uint32_t boff0 = (uint32_t)((wn*32 + (l & 7)) * TPADB + (((l >> 3) & 1) << 4));

    for (int sc = 0; sc < SS/32; sc++) {
        const uint32_t cb = sbase + (sc & 1)*KVSTG;
        uint4 va1, va2, pa1, pa2;
        if (sc < SS/32 - 1) {
            const size_t sb = (size_t)(sc + 1) * 32;
            va1 = *reinterpret_cast<const uint4*>(vv + (sb + s1)*SSTR + d01);
            va2 = *reinterpret_cast<const uint4*>(vv + (sb + s2)*SSTR + d01);
            pa1 = *reinterpret_cast<const uint4*>(pk + (sb + s1)*SSTR + d01);
            pa2 = *reinterpret_cast<const uint4*>(pk + (sb + s2)*SSTR + d01);
        }

#pragma unroll
        for (int ks = 0; ks < 2; ks++) {
            const uint32_t a_b = cb + aoff0 + ks*32;
            const uint32_t b_b = cb + TBYTES + boff0 + ks*32;
            uint32_t ah[4][4], bh[4][2];
#pragma unroll
            for (int mt = 0; mt < 4; mt++) ldsm4(ah[mt], a_b + mt*16*TPADB);
#pragma unroll
            for (int nt = 0; nt < 4; nt++) ldsm2(bh[nt], b_b + nt*8*TPADB);
#pragma unroll
            for (int mt = 0; mt < 4; mt++)
#pragma unroll
                for (int nt = 0; nt < 4; nt++)
                    mma16816h(acc[mt][nt], ah[mt], bh[nt]);
        }

        if (sc < SS/32 - 1) {
            char* nb = sm + ((sc + 1) & 1)*KVSTG;
            __half h8[8];
            *reinterpret_cast<uint4*>(h8) = va1;
#pragma unroll
            for (int j = 0; j < 8; j++) { int i = (j + l) & 7;
                *reinterpret_cast<__half*>(nb + (d01+i)*TPADB + s1*2) = h8[i]; }
            *reinterpret_cast<uint4*>(h8) = va2;
#pragma unroll
            for (int j = 0; j < 8; j++) { int i = (j + l) & 7;
                *reinterpret_cast<__half*>(nb + (d01+i)*TPADB + s2*2) = h8[i]; }
            *reinterpret_cast<uint4*>(h8) = pa1;
#pragma unroll
            for (int j = 0; j < 8; j++) { int i = (j + l) & 7;
                zpart[i] += __half2float(h8[i]);
                *reinterpret_cast<__half*>(nb + TBYTES + (d01+i)*TPADB + s1*2) = h8[i]; }
            *reinterpret_cast<uint4*>(h8) = pa2;
#pragma unroll
            for (int j = 0; j < 8; j++) { int i = (j + l) & 7;
                zpart[i] += __half2float(h8[i]);
                *reinterpret_cast<__half*>(nb + TBYTES + (d01+i)*TPADB + s2*2) = h8[i]; }
        }
        __syncthreads();
    }

#pragma unroll
    for (int i = 0; i < 8; i++) atomicAdd(&zsm[d01 + i], zpart[i]);

    const int gi = l >> 2, ti = l & 3;
    __half* kvb = kvT + (size_t)pair * DHH * DHH;
#pragma unroll
    for (int mt = 0; mt < 4; mt++) {
        const int ra = wm*64 + mt*16 + gi;
        const int rb = ra + 8;
#pragma unroll
        for (int nt = 0; nt < 4; nt++) {
            const int col = wn*32 + nt*8 + ti*2;
            *reinterpret_cast<__half2*>(kvb + ra*DHH + col) =
                __floats2half2_rn(acc[mt][nt][0], acc[mt][nt][1]);
            *reinterpret_cast<__half2*>(kvb + rb*DHH + col) =
                __floats2half2_rn(acc[mt][nt][2], acc[mt][nt][3]);
        }
    }
    __syncthreads();
    if (tid < DHH) z[pair*DHH + tid] = zsm[tid];
}

// ---------------------------------------------------------------------------
// attn via MMA: num = pq_tile @ kvT^T (K=128); den = pq.z; att = num/(den+eps)
// ---------------------------------------------------------------------------
#define TPA 272

__global__ void __launch_bounds__(256) attn_mma(const __half* __restrict__ qkv,
                                                const __half* __restrict__ kvT,
                                                const float* __restrict__ z,
                                                __half* __restrict__ att) {
    extern __shared__ char sm[];
    __shared__ float zsm[DHH];
    __shared__ float dens[128];
    const int s0   = blockIdx.x * 128;
    const int pair = blockIdx.y;
    const size_t base_in  = (size_t)(pair / HH) * NQKV + (size_t)(pair % HH) * DHH;
    const size_t base_out = (size_t)(pair / HH) * DD   + (size_t)(pair % HH) * DHH;
    const __half* pq = qkv + base_in;
    const int tid = threadIdx.x;
    const int l   = tid & 31;
    const int wid = tid >> 5;
    const int wm  = wid >> 2;
    const int wn  = wid & 3;

#pragma unroll
    for (int k = 0; k < 8; k++) {
        int idx = tid + k*256;
        int row = idx >> 4, c16 = idx & 15;
        uint4 q = *reinterpret_cast<const uint4*>(pq + (size_t)(s0 + row)*SSTR + c16*8);
        *reinterpret_cast<uint4*>(sm + row*TPA + c16*16) = q;
        uint4 kvv = *reinterpret_cast<const uint4*>(kvT + (size_t)pair*DHH*DHH + row*DHH + c16*8);
        *reinterpret_cast<uint4*>(sm + 128*TPA + row*TPA + c16*16) = kvv;
    }
    if (tid < DHH) zsm[tid] = z[pair*DHH + tid];
    __syncthreads();

    {
        const int row = tid >> 1, hf = tid & 1;
        const __half2* qr = reinterpret_cast<const __half2*>(sm + row*TPA + hf*128);
        float dsum = 0.f;
#pragma unroll
        for (int j = 0; j < 32; j++) {
            float2 qf = __half22float2(qr[j]);
            dsum += qf.x * zsm[hf*64 + 2*j] + qf.y * zsm[hf*64 + 2*j + 1];
        }
        dsum += __shfl_xor_sync(0xFFFFFFFF, dsum, 1);
        if (hf == 0) dens[row] = dsum;
    }

    float acc[4][4][4];
#pragma unroll
    for (int mt = 0; mt < 4; mt++)
#pragma unroll
        for (int nt = 0; nt < 4; nt++)
#pragma unroll
            for (int i = 0; i < 4; i++) acc[mt][nt][i] = 0.f;

    const uint32_t sbase = smem_u32(sm);
    const uint32_t aoff0 = (uint32_t)((wm*64 + (l & 15)) * TPA + ((l >> 4) << 4));
    const uint32_t boff0 = (uint32_t)(128*TPA + (wn*32 + (l & 7)) * TPA + (((l >> 3) & 1) << 4));

#pragma unroll
    for (int ks = 0; ks < 8; ks++) {
        uint32_t ah[4][4], bh[4][2];
#pragma unroll
        for (int mt = 0; mt < 4; mt++) ldsm4(ah[mt], sbase + aoff0 + ks*32 + mt*16*TPA);
#pragma unroll
        for (int nt = 0; nt < 4; nt++) ldsm2(bh[nt], sbase + boff0 + ks*32 + nt*8*TPA);
#pragma unroll
        for (int mt = 0; mt < 4; mt++)
#pragma unroll
            for (int nt = 0; nt < 4; nt++)
                mma16816h(acc[mt][nt], ah[mt], bh[nt]);
    }
    __syncthreads();

    const int gi = l >> 2, ti = l & 3;
#pragma unroll
    for (int mt = 0; mt < 4; mt++) {
        const int ra = wm*64 + mt*16 + gi;
        const int rb = ra + 8;
        const float ia = 1.f / (dens[ra] + 1e-6f);
        const float ib = 1.f / (dens[rb] + 1e-6f);
#pragma unroll
        for (int nt = 0; nt < 4; nt++) {
            const int col = wn*32 + nt*8 + ti*2;
            *reinterpret_cast<__half2*>(att + (size_t)(s0 + ra)*BDD + base_out + col) =
                __floats2half2_rn(acc[mt][nt][0]*ia, acc[mt][nt][1]*ia);
            *reinterpret_cast<__half2*>(att + (size_t)(s0 + rb)*BDD + base_out + col) =
                __floats2half2_rn(acc[mt][nt][2]*ib, acc[mt][nt][3]*ib);
        }
    }
}

// ---------------------------------------------------------------------------
extern "C" void kernel_launch(void* const* d_in, const int* in_sizes, int n_in,
                              void* d_out, int out_size) {
    const float* x  = (const float*)d_in[0];
    const float* Wq = (const float*)d_in[1];
    const float* bq = (const float*)d_in[2];
    const float* Wk = (const float*)d_in[3];
    const float* bk = (const float*)d_in[4];
    const float* Wv = (const float*)d_in[5];
    const float* bv = (const float*)d_in[6];
    const float* Wo = (const float*)d_in[7];
    const float* bo = (const float*)d_in[8];
    float* out = (float*)d_out;
    (void)in_sizes; (void)n_in; (void)out_size;

    __half *h, *qkv, *att, *w, *pe, *kvT;
    float *z, *bqkv;
    cudaGetSymbolAddress((void**)&h,    g_h);
    cudaGetSymbolAddress((void**)&qkv,  g_qkv);
    cudaGetSymbolAddress((void**)&att,  g_att);
    cudaGetSymbolAddress((void**)&w,    g_w);
    cudaGetSymbolAddress((void**)&pe,   g_pe);
    cudaGetSymbolAddress((void**)&kvT,  g_kvT);
    cudaGetSymbolAddress((void**)&z,    g_z);
    cudaGetSymbolAddress((void**)&bqkv, g_bqkv);

    cudaFuncSetAttribute((const void*)gemm_cpa<0>, cudaFuncAttributeMaxDynamicSharedMemorySize, GSMEM);
    cudaFuncSetAttribute((const void*)gemm_cpa<1>, cudaFuncAttributeMaxDynamicSharedMemorySize, GSMEM);
    cudaFuncSetAttribute((const void*)kvz_mma,  cudaFuncAttributeMaxDynamicSharedMemorySize, KVSMEM);
    const int ASMEM = 2*128*TPA;   // 69632
    cudaFuncSetAttribute((const void*)attn_mma, cudaFuncAttributeMaxDynamicSharedMemorySize, ASMEM);

    const size_t WN = (size_t)DD*DD;

    // #1: weight conversions + bias concat
    conv_all<<<(unsigned)(4*WN/4/256), 256>>>(Wq, Wk, Wv, Wo, bq, bk, bv, w, bqkv);
    // #2: PE table (b-independent)
    pe_table<<<(unsigned)((size_t)SS*DD/4/256), 256>>>(pe);
    // #3: h = x + pe
    pe_add_t<<<(unsigned)((size_t)MM*DD/4/256), 256>>>(x, pe, h);
    // #4: merged QKV GEMM (profiled slot)
    gemm_cpa<0><<<dim3(NQKV/128, MM/128), 256, GSMEM>>>(h, w, bqkv, qkv);
    // #5, #6
    kvz_mma<<<BB*HH, 256, KVSMEM>>>(qkv, kvT, z);
    attn_mma<<<dim3(SS/128, BB*HH), 256, ASMEM>>>(qkv, kvT, z, att);
    // #7: O GEMM
    gemm_cpa<1><<<dim3(DD/128, MM/128), 256, GSMEM>>>(att, w + 3*WN, bo, out);
}

// round 15
// speedup vs baseline: 1.4292x; 1.4292x over previous
#include <cuda_runtime.h>
#include <cuda_fp16.h>
#include <cstdint>
#include <math.h>

#define SS  2048
#define BB  16
#define DD  1024
#define HH  8
#define DHH 128
#define MM  (SS*BB)        // 32768 token rows
#define BDD (BB*DD)        // 16384 (s-stride for DD-stride matrices)
#define NQKV 3072
#define SSTR (BB*NQKV)     // 49152 (s-stride inside qkv)

// ---------------- scratch (device globals; allocation-free) ----------------
__device__ __half g_h   [(size_t)MM*DD];
__device__ __half g_qkv [(size_t)MM*NQKV];  // [m][ q(1024) | k(1024) | v(1024) ]
__device__ __half g_att [(size_t)MM*DD];
__device__ __half g_w   [4][(size_t)DD*DD]; // wq|wk|wv|wo contiguous
__device__ float  g_bqkv[NQKV];
__device__ __half g_pe  [(size_t)SS*DD];    // positional encoding table
__device__ __half g_kvT [BB*HH*DHH*DHH];    // kv^T: [pair][e][d] fp16
__device__ float  g_z   [BB*HH*DHH];

// ---------------- helpers ----------------
__device__ __forceinline__ uint32_t smem_u32(const void* p) {
    uint32_t a;
    asm("{ .reg .u64 t; cvta.to.shared.u64 t, %1; cvt.u32.u64 %0, t; }" : "=r"(a) : "l"(p));
    return a;
}
__device__ __forceinline__ void ldsm4(uint32_t* r, uint32_t a) {
    asm volatile("ldmatrix.sync.aligned.m8n8.x4.shared.b16 {%0,%1,%2,%3}, [%4];"
        : "=r"(r[0]), "=r"(r[1]), "=r"(r[2]), "=r"(r[3]) : "r"(a));
}
__device__ __forceinline__ void ldsm2(uint32_t* r, uint32_t a) {
    asm volatile("ldmatrix.sync.aligned.m8n8.x2.shared.b16 {%0,%1}, [%2];"
        : "=r"(r[0]), "=r"(r[1]) : "r"(a));
}
__device__ __forceinline__ void mma16816h(float* c, const uint32_t* a, const uint32_t* b) {
    asm volatile("mma.sync.aligned.m16n8k16.row.col.f32.f16.f16.f32 "
        "{%0,%1,%2,%3}, {%4,%5,%6,%7}, {%8,%9}, {%0,%1,%2,%3};"
        : "+f"(c[0]), "+f"(c[1]), "+f"(c[2]), "+f"(c[3])
        : "r"(a[0]), "r"(a[1]), "r"(a[2]), "r"(a[3]), "r"(b[0]), "r"(b[1]));
}
// cp.async with L1 caching (.ca) — keeps weight reuse in L1
#define CPA_CA(dst, src) asm volatile("cp.async.ca.shared.global [%0], [%1], 16;" :: "r"(dst), "l"(src) : "memory")
#define CPC()  asm volatile("cp.async.commit_group;" ::: "memory")
#define CPW0() asm volatile("cp.async.wait_group 0;" ::: "memory")
#define CPW1() asm volatile("cp.async.wait_group 1;" ::: "memory")

// ---------------------------------------------------------------------------
// PE table: pe[s][d], b-independent (16x fewer sin/cos than fused version)
// ---------------------------------------------------------------------------
__global__ void pe_table(__half* __restrict__ pe) {
    size_t i4 = (size_t)blockIdx.x * blockDim.x + threadIdx.x;   // SS*DD/4 total
    size_t e  = i4 * 4;
    int d = (int)(e % DD);
    int s = (int)(e / DD);
    const float cc = -9.210340371976184f / (float)DD;
    float a0 = (float)s * expf((float)d * cc);
    float a1 = (float)s * expf((float)(d + 2) * cc);
    __half2* pp = reinterpret_cast<__half2*>(pe) + i4*2;
    pp[0] = __floats2half2_rn(sinf(a0), cosf(a0));
    pp[1] = __floats2half2_rn(sinf(a1), cosf(a1));
}

// h = x + pe[s]  (pure streaming; pe row L2-resident across b)
__global__ void pe_add_t(const float* __restrict__ x, const __half* __restrict__ pe,
                         __half* __restrict__ h) {
    size_t i4 = (size_t)blockIdx.x * blockDim.x + threadIdx.x;   // MM*DD/4 total
    size_t e  = i4 * 4;
    int d = (int)(e % DD);
    int m = (int)(e / DD);
    int s = m / BB;
    float4 xv = reinterpret_cast<const float4*>(x)[i4];
    uint2 pr = *reinterpret_cast<const uint2*>(pe + (size_t)s*DD + d);
    __half2 p0 = *reinterpret_cast<__half2*>(&pr.x);
    __half2 p1 = *reinterpret_cast<__half2*>(&pr.y);
    float2 pf0 = __half22float2(p0);
    float2 pf1 = __half22float2(p1);
    __half2* hp = reinterpret_cast<__half2*>(h) + i4*2;
    hp[0] = __floats2half2_rn(xv.x + pf0.x, xv.y + pf0.y);
    hp[1] = __floats2half2_rn(xv.z + pf1.x, xv.w + pf1.y);
}

// all 4 weight conversions + qkv bias concat in one launch
__global__ void conv_all(const float* __restrict__ w0, const float* __restrict__ w1,
                         const float* __restrict__ w2, const float* __restrict__ w3,
                         const float* __restrict__ bq, const float* __restrict__ bk,
                         const float* __restrict__ bv,
                         __half* __restrict__ dst, float* __restrict__ bqkv) {
    const size_t per = (size_t)DD*DD/4;
    size_t i4 = (size_t)blockIdx.x * blockDim.x + threadIdx.x;
    int wi = (int)(i4 / per);
    size_t off = i4 % per;
    const float* src = (wi == 0) ? w0 : (wi == 1) ? w1 : (wi == 2) ? w2 : w3;
    float4 v = reinterpret_cast<const float4*>(src)[off];
    __half2* dp = reinterpret_cast<__half2*>(dst + (size_t)wi*DD*DD) + off*2;
    dp[0] = __floats2half2_rn(v.x, v.y);
    dp[1] = __floats2half2_rn(v.z, v.w);
    if (i4 < NQKV) {
        int j = (int)i4;
        bqkv[j] = (j < DD) ? bq[j] : (j < 2*DD) ? bk[j - DD] : bv[j - 2*DD];
    }
}

// ---------------------------------------------------------------------------
// cp.async.ca fp16 GEMM — EXACT R13 structure (2-stage, issue-before-wait).
// CTA 128x128, 256 thr (2x4 warps, warp tile 64x32), KC=32.
// MODE 0: A=h; B=wqkv; C=qkv fp16 ldc=NQKV; elu+1 iff ncol<2048.
// MODE 1: A=att; B=wo; C=fp32 out ldc=DD.
// ---------------------------------------------------------------------------
#define KC2   32
#define NKC   (DD/KC2)        // 32
#define TPADB 80              // bytes per padded row (64B data + 16B pad)
#define TBYTES (128*TPADB)    // 10240
#define STG    (2*TBYTES)     // 20480 per stage (A+B)
#define GSMEM  (2*STG)        // 40960 -> 2 CTAs/SM

template<int MODE>
__global__ void __launch_bounds__(256) gemm_cpa(
    const __half* __restrict__ Ag, const __half* __restrict__ Bg,
    const float* __restrict__ bias, void* __restrict__ Cv) {
    extern __shared__ char sm[];
    const int tid = threadIdx.x;
    const int l   = tid & 31;
    const int wid = tid >> 5;
    const int wm  = wid >> 2;       // 0..1
    const int wn  = wid & 3;        // 0..3
    const int m0  = blockIdx.y * 128;
    const int n0  = blockIdx.x * 128;

    const int lrow0 = tid >> 2;      // 0..63
    const int lcol  = tid & 3;       // 16B chunk
    const uint32_t sbase = smem_u32(sm);

    const __half* A1 = Ag + (size_t)(m0 + lrow0)      * DD + lcol*8;
    const __half* A2 = Ag + (size_t)(m0 + lrow0 + 64) * DD + lcol*8;
    const __half* B1 = Bg + (size_t)(n0 + lrow0)      * DD + lcol*8;
    const __half* B2 = Bg + (size_t)(n0 + lrow0 + 64) * DD + lcol*8;
    const uint32_t dA1 = (uint32_t)(lrow0*TPADB + lcol*16);
    const uint32_t dA2 = (uint32_t)((lrow0+64)*TPADB + lcol*16);
    const uint32_t dB1 = TBYTES + dA1;
    const uint32_t dB2 = TBYTES + dA2;

    // prologue: chunk 0 -> stage 0
    {
        const uint32_t sb = sbase;
        CPA_CA(sb + dA1, A1);  CPA_CA(sb + dA2, A2);
        CPA_CA(sb + dB1, B1);  CPA_CA(sb + dB2, B2);
        CPC();
    }

    float acc[4][4][4];
#pragma unroll
    for (int mt = 0; mt < 4; mt++)
#pragma unroll
        for (int nt = 0; nt < 4; nt++)
#pragma unroll
            for (int i = 0; i < 4; i++) acc[mt][nt][i] = 0.f;

    const uint32_t aoff0 = (uint32_t)((wm*64 + (l & 15)) * TPADB + ((l >> 4) << 4));
    const uint32_t boff0 = (uint32_t)(TBYTES + (wn*32 + (l & 7)) * TPADB + (((l >> 3) & 1) << 4));

    for (int c = 0; c < NKC; c++) {
        // issue chunk c+1 into the other stage, then wait for chunk c
        if (c + 1 < NKC) {
            const uint32_t sb = sbase + ((c + 1) & 1)*STG;
            const int ko = (c + 1)*KC2;
            CPA_CA(sb + dA1, A1 + ko);  CPA_CA(sb + dA2, A2 + ko);
            CPA_CA(sb + dB1, B1 + ko);  CPA_CA(sb + dB2, B2 + ko);
            CPC();
            CPW1();   // chunk c complete (only c+1 may remain in flight)
        } else {
            CPW0();
        }
        __syncthreads();

        const uint32_t cb = sbase + (c & 1)*STG;
#pragma unroll
        for (int ks = 0; ks < 2; ks++) {
            uint32_t ah[4][4], bh[4][2];
#pragma unroll
            for (int mt = 0; mt < 4; mt++) ldsm4(ah[mt], cb + aoff0 + ks*32 + mt*16*TPADB);
#pragma unroll
            for (int nt = 0; nt < 4; nt++) ldsm2(bh[nt], cb + boff0 + ks*32 + nt*8*TPADB);
#pragma unroll
            for (int mt = 0; mt < 4; mt++)
#pragma unroll
                for (int nt = 0; nt < 4; nt++)
                    mma16816h(acc[mt][nt], ah[mt], bh[nt]);
        }
        __syncthreads();   // compute(c) done before next iter overwrites stage c&1
    }

    // epilogue
    const int gi = l >> 2, ti = l & 3;
#pragma unroll
    for (int mt = 0; mt < 4; mt++) {
        const int ra = m0 + wm*64 + mt*16 + gi;
        const int rb = ra + 8;
#pragma unroll
        for (int nt = 0; nt < 4; nt++) {
            const int ncol = n0 + wn*32 + nt*8 + ti*2;
            const float b0 = bias[ncol], b1 = bias[ncol + 1];
            float u0 = acc[mt][nt][0] + b0;
            float u1 = acc[mt][nt][1] + b1;
            float u2 = acc[mt][nt][2] + b0;
            float u3 = acc[mt][nt][3] + b1;
            if (MODE == 0) {
                if (ncol < 2048) {   // q,k: elu+1
                    u0 = (u0 > 0.f) ? (u0 + 1.f) : expf(u0);
                    u1 = (u1 > 0.f) ? (u1 + 1.f) : expf(u1);
                    u2 = (u2 > 0.f) ? (u2 + 1.f) : expf(u2);
                    u3 = (u3 > 0.f) ? (u3 + 1.f) : expf(u3);
                }
                __half* C = (__half*)Cv;
                *reinterpret_cast<__half2*>(C + (size_t)ra*NQKV + ncol) = __floats2half2_rn(u0, u1);
                *reinterpret_cast<__half2*>(C + (size_t)rb*NQKV + ncol) = __floats2half2_rn(u2, u3);
            } else {
                float* C = (float*)Cv;
                float2 o01; o01.x = u0; o01.y = u1;
                float2 o23; o23.x = u2; o23.y = u3;
                *reinterpret_cast<float2*>(C + (size_t)ra*DD + ncol) = o01;
                *reinterpret_cast<float2*>(C + (size_t)rb*DD + ncol) = o23;
            }
        }
    }
}

// ---------------------------------------------------------------------------
// kvz via MMA: per pair, kvT[e][d] = sum_s v[s,e]*pk[s,d]; z[d] = sum_s pk[s,d]
// ---------------------------------------------------------------------------
#define KVSTG (2*TBYTES)
#define KVSMEM (2*KVSTG)   // 40960

__global__ void __launch_bounds__(256) kvz_mma(const __half* __restrict__ qkv,
                                               __half* __restrict__ kvT,
                                               float* __restrict__ z) {
    extern __shared__ char sm[];
    __shared__ float zsm[DHH];
    const int pair = blockIdx.x;
    const size_t base = (size_t)(pair / HH) * NQKV + (size_t)(pair % HH) * DHH;
    const __half* pk = qkv + DD   + base;
    const __half* vv = qkv + 2*DD + base;
    const int tid = threadIdx.x;
    const int l   = tid & 31;
    const int wid = tid >> 5;
    const int wm  = wid >> 2;
    const int wn  = wid & 3;

    if (tid < DHH) zsm[tid] = 0.f;

    const int s1 = tid >> 4,        d01 = (tid & 15) << 3;
    const int s2 = (tid + 256) >> 4;
    float zpart[8];
#pragma unroll
    for (int i = 0; i < 8; i++) zpart[i] = 0.f;

    {
        uint4 va1 = *reinterpret_cast<const uint4*>(vv + (size_t)s1*SSTR + d01);
        uint4 va2 = *reinterpret_cast<const uint4*>(vv + (size_t)s2*SSTR + d01);
        uint4 pa1 = *reinterpret_cast<const uint4*>(pk + (size_t)s1*SSTR + d01);
        uint4 pa2 = *reinterpret_cast<const uint4*>(pk + (size_t)s2*SSTR + d01);
        __half h8[8];
        *reinterpret_cast<uint4*>(h8) = va1;
#pragma unroll
        for (int j = 0; j < 8; j++) { int i = (j + l) & 7;
            *reinterpret_cast<__half*>(sm + (d01+i)*TPADB + s1*2) = h8[i]; }
        *reinterpret_cast<uint4*>(h8) = va2;
#pragma unroll
        for (int j = 0; j < 8; j++) { int i = (j + l) & 7;
            *reinterpret_cast<__half*>(sm + (d01+i)*TPADB + s2*2) = h8[i]; }
        *reinterpret_cast<uint4*>(h8) = pa1;
#pragma unroll
        for (int j = 0; j < 8; j++) { int i = (j + l) & 7;
            zpart[i] += __half2float(h8[i]);
            *reinterpret_cast<__half*>(sm + TBYTES + (d01+i)*TPADB + s1*2) = h8[i]; }
        *reinterpret_cast<uint4*>(h8) = pa2;
#pragma unroll
        for (int j = 0; j < 8; j++) { int i = (j + l) & 7;
            zpart[i] += __half2float(h8[i]);
            *reinterpret_cast<__half*>(sm + TBYTES + (d01+i)*TPADB + s2*2) = h8[i]; }
    }
    __syncthreads();

    float acc[4][4][4];
#pragma unroll
    for (int mt = 0; mt < 4; mt++)
#pragma unroll
        for (int nt = 0; nt < 4; nt++)
#pragma unroll
            for (int i = 0; i < 4; i++) acc[mt][nt][i] = 0.f;

    const uint32_t sbase = smem_u32(sm);
    const uint32_t aoff0 = (uint32_t)((wm*64 + (l & 15)) * TPADB + ((l >> 4) << 4));
    const uint32_t boff0 = (uint32_t)((wn*32 + (l & 7)) * TPADB + (((l >> 3) & 1) << 4));

    for (int sc = 0; sc < SS/32; sc++) {
        const uint32_t cb = sbase + (sc & 1)*KVSTG;
        uint4 va1, va2, pa1, pa2;
        if (sc < SS/32 - 1) {
            const size_t sb = (size_t)(sc + 1) * 32;
            va1 = *reinterpret_cast<const uint4*>(vv + (sb + s1)*SSTR + d01);
            va2 = *reinterpret_cast<const uint4*>(vv + (sb + s2)*SSTR + d01);
            pa1 = *reinterpret_cast<const uint4*>(pk + (sb + s1)*SSTR + d01);
            pa2 = *reinterpret_cast<const uint4*>(pk + (sb + s2)*SSTR + d01);
        }

#pragma unroll
        for (int ks = 0; ks < 2; ks++) {
            const uint32_t a_b = cb + aoff0 + ks*32;
            const uint32_t b_b = cb + TBYTES + boff0 + ks*32;
            uint32_t ah[4][4], bh[4][2];
#pragma unroll
            for (int mt = 0; mt < 4; mt++) ldsm4(ah[mt], a_b + mt*16*TPADB);
#pragma unroll
            for (int nt = 0; nt < 4; nt++) ldsm2(bh[nt], b_b + nt*8*TPADB);
#pragma unroll
            for (int mt = 0; mt < 4; mt++)
#pragma unroll
                for (int nt = 0; nt < 4; nt++)
                    mma16816h(acc[mt][nt], ah[mt], bh[nt]);
        }

        if (sc < SS/32 - 1) {
            char* nb = sm + ((sc + 1) & 1)*KVSTG;
            __half h8[8];
            *reinterpret_cast<uint4*>(h8) = va1;
#pragma unroll
            for (int j = 0; j < 8; j++) { int i = (j + l) & 7;
                *reinterpret_cast<__half*>(nb + (d01+i)*TPADB + s1*2) = h8[i]; }
            *reinterpret_cast<uint4*>(h8) = va2;
#pragma unroll
            for (int j = 0; j < 8; j++) { int i = (j + l) & 7;
                *reinterpret_cast<__half*>(nb + (d01+i)*TPADB + s2*2) = h8[i]; }
            *reinterpret_cast<uint4*>(h8) = pa1;
#pragma unroll
            for (int j = 0; j < 8; j++) { int i = (j + l) & 7;
                zpart[i] += __half2float(h8[i]);
                *reinterpret_cast<__half*>(nb + TBYTES + (d01+i)*TPADB + s1*2) = h8[i]; }
            *reinterpret_cast<uint4*>(h8) = pa2;
#pragma unroll
            for (int j = 0; j < 8; j++) { int i = (j + l) & 7;
                zpart[i] += __half2float(h8[i]);
                *reinterpret_cast<__half*>(nb + TBYTES + (d01+i)*TPADB + s2*2) = h8[i]; }
        }
        __syncthreads();
    }

#pragma unroll
    for (int i = 0; i < 8; i++) atomicAdd(&zsm[d01 + i], zpart[i]);

    const int gi = l >> 2, ti = l & 3;
    __half* kvb = kvT + (size_t)pair * DHH * DHH;
#pragma unroll
    for (int mt = 0; mt < 4; mt++) {
        const int ra = wm*64 + mt*16 + gi;
        const int rb = ra + 8;
#pragma unroll
        for (int nt = 0; nt < 4; nt++) {
            const int col = wn*32 + nt*8 + ti*2;
            *reinterpret_cast<__half2*>(kvb + ra*DHH + col) =
                __floats2half2_rn(acc[mt][nt][0], acc[mt][nt][1]);
            *reinterpret_cast<__half2*>(kvb + rb*DHH + col) =
                __floats2half2_rn(acc[mt][nt][2], acc[mt][nt][3]);
        }
    }
    __syncthreads();
    if (tid < DHH) z[pair*DHH + tid] = zsm[tid];
}

// ---------------------------------------------------------------------------
// attn via MMA: num = pq_tile @ kvT^T (K=128); den = pq.z; att = num/(den+eps)
// ---------------------------------------------------------------------------
#define TPA 272

__global__ void __launch_bounds__(256) attn_mma(const __half* __restrict__ qkv,
                                                const __half* __restrict__ kvT,
                                                const float* __restrict__ z,
                                                __half* __restrict__ att) {
    extern __shared__ char sm[];
    __shared__ float zsm[DHH];
    __shared__ float dens[128];
    const int s0   = blockIdx.x * 128;
    const int pair = blockIdx.y;
    const size_t base_in  = (size_t)(pair / HH) * NQKV + (size_t)(pair % HH) * DHH;
    const size_t base_out = (size_t)(pair / HH) * DD   + (size_t)(pair % HH) * DHH;
    const __half* pq = qkv + base_in;
    const int tid = threadIdx.x;
    const int l   = tid & 31;
    const int wid = tid >> 5;
    const int wm  = wid >> 2;
    const int wn  = wid & 3;

#pragma unroll
    for (int k = 0; k < 8; k++) {
        int idx = tid + k*256;
        int row = idx >> 4, c16 = idx & 15;
        uint4 q = *reinterpret_cast<const uint4*>(pq + (size_t)(s0 + row)*SSTR + c16*8);
        *reinterpret_cast<uint4*>(sm + row*TPA + c16*16) = q;
        uint4 kvv = *reinterpret_cast<const uint4*>(kvT + (size_t)pair*DHH*DHH + row*DHH + c16*8);
        *reinterpret_cast<uint4*>(sm + 128*TPA + row*TPA + c16*16) = kvv;
    }
    if (tid < DHH) zsm[tid] = z[pair*DHH + tid];
    __syncthreads();

    {
        const int row = tid >> 1, hf = tid & 1;
        const __half2* qr = reinterpret_cast<const __half2*>(sm + row*TPA + hf*128);
        float dsum = 0.f;
#pragma unroll
        for (int j = 0; j < 32; j++) {
            float2 qf = __half22float2(qr[j]);
            dsum += qf.x * zsm[hf*64 + 2*j] + qf.y * zsm[hf*64 + 2*j + 1];
        }
        dsum += __shfl_xor_sync(0xFFFFFFFF, dsum, 1);
        if (hf == 0) dens[row] = dsum;
    }

    float acc[4][4][4];
#pragma unroll
    for (int mt = 0; mt < 4; mt++)
#pragma unroll
        for (int nt = 0; nt < 4; nt++)
#pragma unroll
            for (int i = 0; i < 4; i++) acc[mt][nt][i] = 0.f;

    const uint32_t sbase = smem_u32(sm);
    const uint32_t aoff0 = (uint32_t)((wm*64 + (l & 15)) * TPA + ((l >> 4) << 4));
    const uint32_t boff0 = (uint32_t)(128*TPA + (wn*32 + (l & 7)) * TPA + (((l >> 3) & 1) << 4));

#pragma unroll
    for (int ks = 0; ks < 8; ks++) {
        uint32_t ah[4][4], bh[4][2];
#pragma unroll
        for (int mt = 0; mt < 4; mt++) ldsm4(ah[mt], sbase + aoff0 + ks*32 + mt*16*TPA);
#pragma unroll
        for (int nt = 0; nt < 4; nt++) ldsm2(bh[nt], sbase + boff0 + ks*32 + nt*8*TPA);
#pragma unroll
        for (int mt = 0; mt < 4; mt++)
#pragma unroll
            for (int nt = 0; nt < 4; nt++)
                mma16816h(acc[mt][nt], ah[mt], bh[nt]);
    }
    __syncthreads();

    const int gi = l >> 2, ti = l & 3;
#pragma unroll
    for (int mt = 0; mt < 4; mt++) {
        const int ra = wm*64 + mt*16 + gi;
        const int rb = ra + 8;
        const float ia = 1.f / (dens[ra] + 1e-6f);
        const float ib = 1.f / (dens[rb] + 1e-6f);
#pragma unroll
        for (int nt = 0; nt < 4; nt++) {
            const int col = wn*32 + nt*8 + ti*2;
            *reinterpret_cast<__half2*>(att + (size_t)(s0 + ra)*BDD + base_out + col) =
                __floats2half2_rn(acc[mt][nt][0]*ia, acc[mt][nt][1]*ia);
            *reinterpret_cast<__half2*>(att + (size_t)(s0 + rb)*BDD + base_out + col) =
                __floats2half2_rn(acc[mt][nt][2]*ib, acc[mt][nt][3]*ib);
        }
    }
}

// ---------------------------------------------------------------------------
extern "C" void kernel_launch(void* const* d_in, const int* in_sizes, int n_in,
                              void* d_out, int out_size) {
    const float* x  = (const float*)d_in[0];
    const float* Wq = (const float*)d_in[1];
    const float* bq = (const float*)d_in[2];
    const float* Wk = (const float*)d_in[3];
    const float* bk = (const float*)d_in[4];
    const float* Wv = (const float*)d_in[5];
    const float* bv = (const float*)d_in[6];
    const float* Wo = (const float*)d_in[7];
    const float* bo = (const float*)d_in[8];
    float* out = (float*)d_out;
    (void)in_sizes; (void)n_in; (void)out_size;

    __half *h, *qkv, *att, *w, *pe, *kvT;
    float *z, *bqkv;
    cudaGetSymbolAddress((void**)&h,    g_h);
    cudaGetSymbolAddress((void**)&qkv,  g_qkv);
    cudaGetSymbolAddress((void**)&att,  g_att);
    cudaGetSymbolAddress((void**)&w,    g_w);
    cudaGetSymbolAddress((void**)&pe,   g_pe);
    cudaGetSymbolAddress((void**)&kvT,  g_kvT);
    cudaGetSymbolAddress((void**)&z,    g_z);
    cudaGetSymbolAddress((void**)&bqkv, g_bqkv);

    cudaFuncSetAttribute((const void*)gemm_cpa<0>, cudaFuncAttributeMaxDynamicSharedMemorySize, GSMEM);
    cudaFuncSetAttribute((const void*)gemm_cpa<1>, cudaFuncAttributeMaxDynamicSharedMemorySize, GSMEM);
    cudaFuncSetAttribute((const void*)kvz_mma,  cudaFuncAttributeMaxDynamicSharedMemorySize, KVSMEM);
    const int ASMEM = 2*128*TPA;   // 69632
    cudaFuncSetAttribute((const void*)attn_mma, cudaFuncAttributeMaxDynamicSharedMemorySize, ASMEM);

    const size_t WN = (size_t)DD*DD;

    // #1: weight conversions + bias concat
    conv_all<<<(unsigned)(4*WN/4/256), 256>>>(Wq, Wk, Wv, Wo, bq, bk, bv, w, bqkv);
    // #2: PE table (b-independent)
    pe_table<<<(unsigned)((size_t)SS*DD/4/256), 256>>>(pe);
    // #3: h = x + pe
    pe_add_t<<<(unsigned)((size_t)MM*DD/4/256), 256>>>(x, pe, h);
    // #4: merged QKV GEMM (profiled slot)
    gemm_cpa<0><<<dim3(NQKV/128, MM/128), 256, GSMEM>>>(h, w, bqkv, qkv);
    // #5, #6
    kvz_mma<<<BB*HH, 256, KVSMEM>>>(qkv, kvT, z);
    attn_mma<<<dim3(SS/128, BB*HH), 256, ASMEM>>>(qkv, kvT, z, att);
    // #7: O GEMM
    gemm_cpa<1><<<dim3(DD/128, MM/128), 256, GSMEM>>>(att, w + 3*WN, bo, out);
}

// round 16
// speedup vs baseline: 1.6576x; 1.1598x over previous
#include <cuda_runtime.h>
#include <cuda_fp16.h>
#include <cstdint>
#include <math.h>

#define SS  2048
#define BB  16
#define DD  1024
#define HH  8
#define DHH 128
#define MM  (SS*BB)        // 32768 token rows
#define BDD (BB*DD)        // 16384 (s-stride for DD-stride matrices)
#define NQKV 3072
#define SSTR (BB*NQKV)     // 49152 (s-stride inside qkv)

// ---------------- scratch (device globals; allocation-free) ----------------
__device__ __half g_h   [(size_t)MM*DD];
__device__ __half g_qkv [(size_t)MM*NQKV];  // [m][ q(1024) | k(1024) | v(1024) ]
__device__ __half g_att [(size_t)MM*DD];
__device__ __half g_w   [4][(size_t)DD*DD]; // wq|wk|wv|wo contiguous
__device__ float  g_bqkv[NQKV];
__device__ __half g_pe  [(size_t)SS*DD];    // positional encoding table
__device__ __half g_kvT [BB*HH*DHH*DHH];    // kv^T: [pair][e][d] fp16
__device__ float  g_z   [BB*HH*DHH];

// ---------------- helpers ----------------
__device__ __forceinline__ uint32_t smem_u32(const void* p) {
    uint32_t a;
    asm("{ .reg .u64 t; cvta.to.shared.u64 t, %1; cvt.u32.u64 %0, t; }" : "=r"(a) : "l"(p));
    return a;
}
__device__ __forceinline__ void ldsm4(uint32_t* r, uint32_t a) {
    asm volatile("ldmatrix.sync.aligned.m8n8.x4.shared.b16 {%0,%1,%2,%3}, [%4];"
        : "=r"(r[0]), "=r"(r[1]), "=r"(r[2]), "=r"(r[3]) : "r"(a));
}
__device__ __forceinline__ void ldsm2(uint32_t* r, uint32_t a) {
    asm volatile("ldmatrix.sync.aligned.m8n8.x2.shared.b16 {%0,%1}, [%2];"
        : "=r"(r[0]), "=r"(r[1]) : "r"(a));
}
__device__ __forceinline__ void mma16816h(float* c, const uint32_t* a, const uint32_t* b) {
    asm volatile("mma.sync.aligned.m16n8k16.row.col.f32.f16.f16.f32 "
        "{%0,%1,%2,%3}, {%4,%5,%6,%7}, {%8,%9}, {%0,%1,%2,%3};"
        : "+f"(c[0]), "+f"(c[1]), "+f"(c[2]), "+f"(c[3])
        : "r"(a[0]), "r"(a[1]), "r"(a[2]), "r"(a[3]), "r"(b[0]), "r"(b[1]));
}
#define CPA_CA(dst, src) asm volatile("cp.async.ca.shared.global [%0], [%1], 16;" :: "r"(dst), "l"(src) : "memory")
#define CPC()  asm volatile("cp.async.commit_group;" ::: "memory")
#define CPW0() asm volatile("cp.async.wait_group 0;" ::: "memory")
#define CPW1() asm volatile("cp.async.wait_group 1;" ::: "memory")

// ---------------------------------------------------------------------------
// PE table + streaming add
// ---------------------------------------------------------------------------
__global__ void pe_table(__half* __restrict__ pe) {
    size_t i4 = (size_t)blockIdx.x * blockDim.x + threadIdx.x;
    size_t e  = i4 * 4;
    int d = (int)(e % DD);
    int s = (int)(e / DD);
    const float cc = -9.210340371976184f / (float)DD;
    float a0 = (float)s * expf((float)d * cc);
    float a1 = (float)s * expf((float)(d + 2) * cc);
    __half2* pp = reinterpret_cast<__half2*>(pe) + i4*2;
    pp[0] = __floats2half2_rn(sinf(a0), cosf(a0));
    pp[1] = __floats2half2_rn(sinf(a1), cosf(a1));
}

__global__ void pe_add_t(const float* __restrict__ x, const __half* __restrict__ pe,
                         __half* __restrict__ h) {
    size_t i4 = (size_t)blockIdx.x * blockDim.x + threadIdx.x;
    size_t e  = i4 * 4;
    int d = (int)(e % DD);
    int m = (int)(e / DD);
    int s = m / BB;
    float4 xv = reinterpret_cast<const float4*>(x)[i4];
    uint2 pr = *reinterpret_cast<const uint2*>(pe + (size_t)s*DD + d);
    __half2 p0 = *reinterpret_cast<__half2*>(&pr.x);
    __half2 p1 = *reinterpret_cast<__half2*>(&pr.y);
    float2 pf0 = __half22float2(p0);
    float2 pf1 = __half22float2(p1);
    __half2* hp = reinterpret_cast<__half2*>(h) + i4*2;
    hp[0] = __floats2half2_rn(xv.x + pf0.x, xv.y + pf0.y);
    hp[1] = __floats2half2_rn(xv.z + pf1.x, xv.w + pf1.y);
}

__global__ void conv_all(const float* __restrict__ w0, const float* __restrict__ w1,
                         const float* __restrict__ w2, const float* __restrict__ w3,
                         const float* __restrict__ bq, const float* __restrict__ bk,
                         const float* __restrict__ bv,
                         __half* __restrict__ dst, float* __restrict__ bqkv) {
    const size_t per = (size_t)DD*DD/4;
    size_t i4 = (size_t)blockIdx.x * blockDim.x + threadIdx.x;
    int wi = (int)(i4 / per);
    size_t off = i4 % per;
    const float* src = (wi == 0) ? w0 : (wi == 1) ? w1 : (wi == 2) ? w2 : w3;
    float4 v = reinterpret_cast<const float4*>(src)[off];
    __half2* dp = reinterpret_cast<__half2*>(dst + (size_t)wi*DD*DD) + off*2;
    dp[0] = __floats2half2_rn(v.x, v.y);
    dp[1] = __floats2half2_rn(v.z, v.w);
    if (i4 < NQKV) {
        int j = (int)i4;
        bqkv[j] = (j < DD) ? bq[j] : (j < 2*DD) ? bk[j - DD] : bv[j - 2*DD];
    }
}

// ---------------------------------------------------------------------------
// cp.async.ca fp16 GEMM — R13 pipeline, KC=64 (half the barriers).
// CTA 128x128, 256 thr (2x4 warps, warp tile 64x32).
// smem: rows 128B data padded to 144B; 2 tiles x 2 stages = 72KB.
// MODE 0: A=h; B=wqkv; C=qkv fp16 ldc=NQKV; elu+1 iff ncol<2048.
// MODE 1: A=att; B=wo; C=fp32 out ldc=DD.
// ---------------------------------------------------------------------------
#define KC64   64
#define NKC64  (DD/KC64)       // 16
#define TPAD64 144             // 128B data + 16B pad (144%128=16 -> conflict-free)
#define TB64   (128*TPAD64)    // 18432
#define STG64  (2*TB64)        // 36864 per stage (A+B)
#define GSMEM64 (2*STG64)      // 73728 -> 2 CTAs/SM

template<int MODE>
__global__ void __launch_bounds__(256) gemm_cpa(
    const __half* __restrict__ Ag, const __half* __restrict__ Bg,
    const float* __restrict__ bias, void* __restrict__ Cv) {
    extern __shared__ char sm[];
    const int tid = threadIdx.x;
    const int l   = tid & 31;
    const int wid = tid >> 5;
    const int wm  = wid >> 2;       // 0..1
    const int wn  = wid & 3;        // 0..3
    const int m0  = blockIdx.y * 128;
    const int n0  = blockIdx.x * 128;

    // loader: c16 = tid&7 (16B column), rows = (tid>>3) + {0,32,64,96}
    const int c16  = tid & 7;
    const int row0 = tid >> 3;      // 0..31
    const uint32_t sbase = smem_u32(sm);

    const __half* Abase = Ag + (size_t)m0 * DD + c16*8;
    const __half* Bbase = Bg + (size_t)n0 * DD + c16*8;

    // prologue: chunk 0 -> stage 0
    {
#pragma unroll
        for (int j = 0; j < 4; j++) {
            int r = row0 + j*32;
            CPA_CA(sbase + r*TPAD64 + c16*16,         Abase + (size_t)r*DD);
            CPA_CA(sbase + TB64 + r*TPAD64 + c16*16,  Bbase + (size_t)r*DD);
        }
        CPC();
    }

    float acc[4][4][4];
#pragma unroll
    for (int mt = 0; mt < 4; mt++)
#pragma unroll
        for (int nt = 0; nt < 4; nt++)
#pragma unroll
            for (int i = 0; i < 4; i++) acc[mt][nt][i] = 0.f;

    const uint32_t aoff0 = (uint32_t)((wm*64 + (l & 15)) * TPAD64 + ((l >> 4) << 4));
    const uint32_t boff0 = (uint32_t)(TB64 + (wn*32 + (l & 7)) * TPAD64 + (((l >> 3) & 1) << 4));

    for (int c = 0; c < NKC64; c++) {
        // issue chunk c+1 into the other stage, then wait for chunk c
        if (c + 1 < NKC64) {
            const uint32_t sb = sbase + ((c + 1) & 1)*STG64;
            const int ko = (c + 1)*KC64;
#pragma unroll
            for (int j = 0; j < 4; j++) {
                int r = row0 + j*32;
                CPA_CA(sb + r*TPAD64 + c16*16,        Abase + (size_t)r*DD + ko);
                CPA_CA(sb + TB64 + r*TPAD64 + c16*16, Bbase + (size_t)r*DD + ko);
            }
            CPC();
            CPW1();
        } else {
            CPW0();
        }
        __syncthreads();

        const uint32_t cb = sbase + (c & 1)*STG64;
#pragma unroll
        for (int ks = 0; ks < 4; ks++) {
            uint32_t ah[4][4], bh[4][2];
#pragma unroll
            for (int mt = 0; mt < 4; mt++) ldsm4(ah[mt], cb + aoff0 + ks*32 + mt*16*TPAD64);
#pragma unroll
            for (int nt = 0; nt < 4; nt++) ldsm2(bh[nt], cb + boff0 + ks*32 + nt*8*TPAD64);
#pragma unroll
            for (int mt = 0; mt < 4; mt++)
#pragma unroll
                for (int nt = 0; nt < 4; nt++)
                    mma16816h(acc[mt][nt], ah[mt], bh[nt]);
        }
        __syncthreads();
    }

    // epilogue
    const int gi = l >> 2, ti = l & 3;
#pragma unroll
    for (int mt = 0; mt < 4; mt++) {
        const int ra = m0 + wm*64 + mt*16 + gi;
        const int rb = ra + 8;
#pragma unroll
        for (int nt = 0; nt < 4; nt++) {
            const int ncol = n0 + wn*32 + nt*8 + ti*2;
            const float b0 = bias[ncol], b1 = bias[ncol + 1];
            float u0 = acc[mt][nt][0] + b0;
            float u1 = acc[mt][nt][1] + b1;
            float u2 = acc[mt][nt][2] + b0;
            float u3 = acc[mt][nt][3] + b1;
            if (MODE == 0) {
                if (ncol < 2048) {   // q,k: elu+1
                    u0 = (u0 > 0.f) ? (u0 + 1.f) : expf(u0);
                    u1 = (u1 > 0.f) ? (u1 + 1.f) : expf(u1);
                    u2 = (u2 > 0.f) ? (u2 + 1.f) : expf(u2);
                    u3 = (u3 > 0.f) ? (u3 + 1.f) : expf(u3);
                }
                __half* C = (__half*)Cv;
                *reinterpret_cast<__half2*>(C + (size_t)ra*NQKV + ncol) = __floats2half2_rn(u0, u1);
                *reinterpret_cast<__half2*>(C + (size_t)rb*NQKV + ncol) = __floats2half2_rn(u2, u3);
            } else {
                float* C = (float*)Cv;
                float2 o01; o01.x = u0; o01.y = u1;
                float2 o23; o23.x = u2; o23.y = u3;
                *reinterpret_cast<float2*>(C + (size_t)ra*DD + ncol) = o01;
                *reinterpret_cast<float2*>(C + (size_t)rb*DD + ncol) = o23;
            }
        }
    }
}

// ---------------------------------------------------------------------------
// kvz via MMA (unchanged, own pad constants)
// ---------------------------------------------------------------------------
#define TPADB 80
#define TBYTES (128*TPADB)    // 10240
#define KVSTG (2*TBYTES)
#define KVSMEM (2*KVSTG)      // 40960

__global__ void __launch_bounds__(256) kvz_mma(const __half* __restrict__ qkv,
                                               __half* __restrict__ kvT,
                                               float* __restrict__ z) {
    extern __shared__ char sm[];
    __shared__ float zsm[DHH];
    const int pair = blockIdx.x;
    const size_t base = (size_t)(pair / HH) * NQKV + (size_t)(pair % HH) * DHH;
    const __half* pk = qkv + DD   + base;
    const __half* vv = qkv + 2*DD + base;
    const int tid = threadIdx.x;
    const int l   = tid & 31;
    const int wid = tid >> 5;
    const int wm  = wid >> 2;
    const int wn  = wid & 3;

    if (tid < DHH) zsm[tid] = 0.f;

    const int s1 = tid >> 4,        d01 = (tid & 15) << 3;
    const int s2 = (tid + 256) >> 4;
    float zpart[8];
#pragma unroll
    for (int i = 0; i < 8; i++) zpart[i] = 0.f;

    {
        uint4 va1 = *reinterpret_cast<const uint4*>(vv + (size_t)s1*SSTR + d01);
        uint4 va2 = *reinterpret_cast<const uint4*>(vv + (size_t)s2*SSTR + d01);
        uint4 pa1 = *reinterpret_cast<const uint4*>(pk + (size_t)s1*SSTR + d01);
        uint4 pa2 = *reinterpret_cast<const uint4*>(pk + (size_t)s2*SSTR + d01);
        __half h8[8];
        *reinterpret_cast<uint4*>(h8) = va1;
#pragma unroll
        for (int j = 0; j < 8; j++) { int i = (j + l) & 7;
            *reinterpret_cast<__half*>(sm + (d01+i)*TPADB + s1*2) = h8[i]; }
        *reinterpret_cast<uint4*>(h8) = va2;
#pragma unroll
        for (int j = 0; j < 8; j++) { int i = (j + l) & 7;
            *reinterpret_cast<__half*>(sm + (d01+i)*TPADB + s2*2) = h8[i]; }
        *reinterpret_cast<uint4*>(h8) = pa1;
#pragma unroll
        for (int j = 0; j < 8; j++) { int i = (j + l) & 7;
            zpart[i] += __half2float(h8[i]);
            *reinterpret_cast<__half*>(sm + TBYTES + (d01+i)*TPADB + s1*2) = h8[i]; }
        *reinterpret_cast<uint4*>(h8) = pa2;
#pragma unroll
        for (int j = 0; j < 8; j++) { int i = (j + l) & 7;
            zpart[i] += __half2float(h8[i]);
            *reinterpret_cast<__half*>(sm + TBYTES + (d01+i)*TPADB + s2*2) = h8[i]; }
    }
    __syncthreads();

    float acc[4][4][4];
#pragma unroll
    for (int mt = 0; mt < 4; mt++)
#pragma unroll
        for (int nt = 0; nt < 4; nt++)
#pragma unroll
            for (int i = 0; i < 4; i++) acc[mt][nt][i] = 0.f;

    const uint32_t sbase = smem_u32(sm);
    const uint32_t aoff0 = (uint32_t)((wm*64 + (l & 15)) * TPADB + ((l >> 4) << 4));
    const uint32_t boff0 = (uint32_t)((wn*32 + (l & 7)) * TPADB + (((l >> 3) & 1) << 4));

    for (int sc = 0; sc < SS/32; sc++) {
        const uint32_t cb = sbase + (sc & 1)*KVSTG;
        uint4 va1, va2, pa1, pa2;
        if (sc < SS/32 - 1) {
            const size_t sb = (size_t)(sc + 1) * 32;
            va1 = *reinterpret_cast<const uint4*>(vv + (sb + s1)*SSTR + d01);
            va2 = *reinterpret_cast<const uint4*>(vv + (sb + s2)*SSTR + d01);
            pa1 = *reinterpret_cast<const uint4*>(pk + (sb + s1)*SSTR + d01);
            pa2 = *reinterpret_cast<const uint4*>(pk + (sb + s2)*SSTR + d01);
        }

#pragma unroll
        for (int ks = 0; ks < 2; ks++) {
            const uint32_t a_b = cb + aoff0 + ks*32;
            const uint32_t b_b = cb + TBYTES + boff0 + ks*32;
            uint32_t ah[4][4], bh[4][2];
#pragma unroll
            for (int mt = 0; mt < 4; mt++) ldsm4(ah[mt], a_b + mt*16*TPADB);
#pragma unroll
            for (int nt = 0; nt < 4; nt++) ldsm2(bh[nt], b_b + nt*8*TPADB);
#pragma unroll
            for (int mt = 0; mt < 4; mt++)
#pragma unroll
                for (int nt = 0; nt < 4; nt++)
                    mma16816h(acc[mt][nt], ah[mt], bh[nt]);
        }

        if (sc < SS/32 - 1) {
            char* nb = sm + ((sc + 1) & 1)*KVSTG;
            __half h8[8];
            *reinterpret_cast<uint4*>(h8) = va1;
#pragma unroll
            for (int j = 0; j < 8; j++) { int i = (j + l) & 7;
                *reinterpret_cast<__half*>(nb + (d01+i)*TPADB + s1*2) = h8[i]; }
            *reinterpret_cast<uint4*>(h8) = va2;
#pragma unroll
            for (int j = 0; j < 8; j++) { int i = (j + l) & 7;
                *reinterpret_cast<__half*>(nb + (d01+i)*TPADB + s2*2) = h8[i]; }
            *reinterpret_cast<uint4*>(h8) = pa1;
#pragma unroll
            for (int j = 0; j < 8; j++) { int i = (j + l) & 7;
                zpart[i] += __half2float(h8[i]);
                *reinterpret_cast<__half*>(nb + TBYTES + (d01+i)*TPADB + s1*2) = h8[i]; }
            *reinterpret_cast<uint4*>(h8) = pa2;
#pragma unroll
            for (int j = 0; j < 8; j++) { int i = (j + l) & 7;
                zpart[i] += __half2float(h8[i]);
                *reinterpret_cast<__half*>(nb + TBYTES + (d01+i)*TPADB + s2*2) = h8[i]; }
        }
        __syncthreads();
    }

#pragma unroll
    for (int i = 0; i < 8; i++) atomicAdd(&zsm[d01 + i], zpart[i]);

    const int gi = l >> 2, ti = l & 3;
    __half* kvb = kvT + (size_t)pair * DHH * DHH;
#pragma unroll
    for (int mt = 0; mt < 4; mt++) {
        const int ra = wm*64 + mt*16 + gi;
        const int rb = ra + 8;
#pragma unroll
        for (int nt = 0; nt < 4; nt++) {
            const int col = wn*32 + nt*8 + ti*2;
            *reinterpret_cast<__half2*>(kvb + ra*DHH + col) =
                __floats2half2_rn(acc[mt][nt][0], acc[mt][nt][1]);
            *reinterpret_cast<__half2*>(kvb + rb*DHH + col) =
                __floats2half2_rn(acc[mt][nt][2], acc[mt][nt][3]);
        }
    }
    __syncthreads();
    if (tid < DHH) z[pair*DHH + tid] = zsm[tid];
}

// ---------------------------------------------------------------------------
// attn via MMA (unchanged)
// ---------------------------------------------------------------------------
#define TPA 272

__global__ void __launch_bounds__(256) attn_mma(const __half* __restrict__ qkv,
                                                const __half* __restrict__ kvT,
                                                const float* __restrict__ z,
                                                __half* __restrict__ att) {
    extern __shared__ char sm[];
    __shared__ float zsm[DHH];
    __shared__ float dens[128];
    const int s0   = blockIdx.x * 128;
    const int pair = blockIdx.y;
    const size_t base_in  = (size_t)(pair / HH) * NQKV + (size_t)(pair % HH) * DHH;
    const size_t base_out = (size_t)(pair / HH) * DD   + (size_t)(pair % HH) * DHH;
    const __half* pq = qkv + base_in;
    const int tid = threadIdx.x;
    const int l   = tid & 31;
    const int wid = tid >> 5;
    const int wm  = wid >> 2;
    const int wn  = wid & 3;

#pragma unroll
    for (int k = 0; k < 8; k++) {
        int idx = tid + k*256;
        int row = idx >> 4, c16 = idx & 15;
        uint4 q = *reinterpret_cast<const uint4*>(pq + (size_t)(s0 + row)*SSTR + c16*8);
        *reinterpret_cast<uint4*>(sm + row*TPA + c16*16) = q;
        uint4 kvv = *reinterpret_cast<const uint4*>(kvT + (size_t)pair*DHH*DHH + row*DHH + c16*8);
        *reinterpret_cast<uint4*>(sm + 128*TPA + row*TPA + c16*16) = kvv;
    }
    if (tid < DHH) zsm[tid] = z[pair*DHH + tid];
    __syncthreads();

    {
        const int row = tid >> 1, hf = tid & 1;
        const __half2* qr = reinterpret_cast<const __half2*>(sm + row*TPA + hf*128);
        float dsum = 0.f;
#pragma unroll
        for (int j = 0; j < 32; j++) {
            float2 qf = __half22float2(qr[j]);
            dsum += qf.x * zsm[hf*64 + 2*j] + qf.y * zsm[hf*64 + 2*j + 1];
        }
        dsum += __shfl_xor_sync(0xFFFFFFFF, dsum, 1);
        if (hf == 0) dens[row] = dsum;
    }

    float acc[4][4][4];
#pragma unroll
    for (int mt = 0; mt < 4; mt++)
#pragma unroll
        for (int nt = 0; nt < 4; nt++)
#pragma unroll
            for (int i = 0; i < 4; i++) acc[mt][nt][i] = 0.f;

    const uint32_t sbase = smem_u32(sm);
    const uint32_t aoff0 = (uint32_t)((wm*64 + (l & 15)) * TPA + ((l >> 4) << 4));
    const uint32_t boff0 = (uint32_t)(128*TPA + (wn*32 + (l & 7)) * TPA + (((l >> 3) & 1) << 4));

#pragma unroll
    for (int ks = 0; ks < 8; ks++) {
        uint32_t ah[4][4], bh[4][2];
#pragma unroll
        for (int mt = 0; mt < 4; mt++) ldsm4(ah[mt], sbase + aoff0 + ks*32 + mt*16*TPA);
#pragma unroll
        for (int nt = 0; nt < 4; nt++) ldsm2(bh[nt], sbase + boff0 + ks*32 + nt*8*TPA);
#pragma unroll
        for (int mt = 0; mt < 4; mt++)
#pragma unroll
            for (int nt = 0; nt < 4; nt++)
                mma16816h(acc[mt][nt], ah[mt], bh[nt]);
    }
    __syncthreads();

    const int gi = l >> 2, ti = l & 3;
#pragma unroll
    for (int mt = 0; mt < 4; mt++) {
        const int ra = wm*64 + mt*16 + gi;
        const int rb = ra + 8;
        const float ia = 1.f / (dens[ra] + 1e-6f);
        const float ib = 1.f / (dens[rb] + 1e-6f);
#pragma unroll
        for (int nt = 0; nt < 4; nt++) {
            const int col = wn*32 + nt*8 + ti*2;
            *reinterpret_cast<__half2*>(att + (size_t)(s0 + ra)*BDD + base_out + col) =
                __floats2half2_rn(acc[mt][nt][0]*ia, acc[mt][nt][1]*ia);
            *reinterpret_cast<__half2*>(att + (size_t)(s0 + rb)*BDD + base_out + col) =
                __floats2half2_rn(acc[mt][nt][2]*ib, acc[mt][nt][3]*ib);
        }
    }
}

// ---------------------------------------------------------------------------
extern "C" void kernel_launch(void* const* d_in, const int* in_sizes, int n_in,
                              void* d_out, int out_size) {
    const float* x  = (const float*)d_in[0];
    const float* Wq = (const float*)d_in[1];
    const float* bq = (const float*)d_in[2];
    const float* Wk = (const float*)d_in[3];
    const float* bk = (const float*)d_in[4];
    const float* Wv = (const float*)d_in[5];
    const float* bv = (const float*)d_in[6];
    const float* Wo = (const float*)d_in[7];
    const float* bo = (const float*)d_in[8];
    float* out = (float*)d_out;
    (void)in_sizes; (void)n_in; (void)out_size;

    __half *h, *qkv, *att, *w, *pe, *kvT;
    float *z, *bqkv;
    cudaGetSymbolAddress((void**)&h,    g_h);
    cudaGetSymbolAddress((void**)&qkv,  g_qkv);
    cudaGetSymbolAddress((void**)&att,  g_att);
    cudaGetSymbolAddress((void**)&w,    g_w);
    cudaGetSymbolAddress((void**)&pe,   g_pe);
    cudaGetSymbolAddress((void**)&kvT,  g_kvT);
    cudaGetSymbolAddress((void**)&z,    g_z);
    cudaGetSymbolAddress((void**)&bqkv, g_bqkv);

    cudaFuncSetAttribute((const void*)gemm_cpa<0>, cudaFuncAttributeMaxDynamicSharedMemorySize, GSMEM64);
    cudaFuncSetAttribute((const void*)gemm_cpa<1>, cudaFuncAttributeMaxDynamicSharedMemorySize, GSMEM64);
    cudaFuncSetAttribute((const void*)kvz_mma,  cudaFuncAttributeMaxDynamicSharedMemorySize, KVSMEM);
    const int ASMEM = 2*128*TPA;   // 69632
    cudaFuncSetAttribute((const void*)attn_mma, cudaFuncAttributeMaxDynamicSharedMemorySize, ASMEM);

    const size_t WN = (size_t)DD*DD;

    // #1: weight conversions + bias concat
    conv_all<<<(unsigned)(4*WN/4/256), 256>>>(Wq, Wk, Wv, Wo, bq, bk, bv, w, bqkv);
    // #2: PE table
    pe_table<<<(unsigned)((size_t)SS*DD/4/256), 256>>>(pe);
    // #3: h = x + pe
    pe_add_t<<<(unsigned)((size_t)MM*DD/4/256), 256>>>(x, pe, h);
    // #4: merged QKV GEMM (profiled slot)
    gemm_cpa<0><<<dim3(NQKV/128, MM/128), 256, GSMEM64>>>(h, w, bqkv, qkv);
    // #5, #6
    kvz_mma<<<BB*HH, 256, KVSMEM>>>(qkv, kvT, z);
    attn_mma<<<dim3(SS/128, BB*HH), 256, ASMEM>>>(qkv, kvT, z, att);
    // #7: O GEMM
    gemm_cpa<1><<<dim3(DD/128, MM/128), 256, GSMEM64>>>(att, w + 3*WN, bo, out);
}